// round 1
// baseline (speedup 1.0000x reference)
#include <cuda_runtime.h>
#include <cstdint>

// RandomizedOscillatorsNetwork: B=128, T=1024, I=64, H=512, dt=0.042
//
// Persistent-kernel design:
//   grid = 128 CTAs = 16 batch-groups (8 batches each) x 8 column-slices (64 cols each)
//   Each CTA holds [h2h ; x2h][:, its 64 cols] as an augmented K=576 weight matrix in SMEM
//   (loaded once). Per step: k-split FMA matvec for its (8 batch x 64 col) tile,
//   elementwise oscillator update, hy exchange among the 8 column-CTAs of the group
//   via a double-buffered L2 buffer + one release/acquire counter barrier per step.

#define DT_F      0.042f
#define B_        128
#define T_        1024
#define I_        64
#define H_        512
#define KAUG      576           // H_ + I_
#define NCOL      8             // column CTAs per batch group
#define NGRP      16            // batch groups
#define BC        8             // batches per CTA
#define CC        64            // columns per CTA
#define WPITCH    580           // floats per W_s row (4*odd -> conflict-free float4 LDS)
#define NTHREADS  512
#define KSLICES   8
#define KCHUNK    (KAUG / KSLICES)      // 72 floats
#define KCHUNK4   (KCHUNK / 4)          // 18 float4
#define AROW4     (KAUG / 4)            // 144 float4 per a_s row

// Scratch (static device globals; no allocation)
__device__ unsigned g_bar[NGRP];
__device__ float    g_hy_ex[2][NGRP][BC][H_];

__device__ __forceinline__ unsigned ld_acquire_u32(const unsigned* p) {
    unsigned v;
    asm volatile("ld.acquire.gpu.u32 %0, [%1];" : "=r"(v) : "l"(p) : "memory");
    return v;
}
__device__ __forceinline__ void red_release_add(unsigned* p, unsigned v) {
    asm volatile("red.release.gpu.global.add.u32 [%0], %1;" :: "l"(p), "r"(v) : "memory");
}

__global__ void ron_init_kernel() {
    if (threadIdx.x < NGRP) g_bar[threadIdx.x] = 0u;
}

__global__ void __launch_bounds__(NTHREADS, 1)
ron_scan_kernel(const float* __restrict__ x,     // [B, T, I]
                const float* __restrict__ x2h,   // [I, H]
                const float* __restrict__ h2h,   // [H, H]  (k-major: h2h[k][h])
                const float* __restrict__ bias,  // [H]
                const float* __restrict__ gamma_, // [H]
                const float* __restrict__ eps_,  // [H]
                float* __restrict__ out,         // [B*T*H] states (+ optional [B*H] tail)
                int write_tail)
{
    extern __shared__ float smem[];
    float* W_s     = smem;                       // [CC][WPITCH]  c-major augmented weights
    float* a_s     = W_s + CC * WPITCH;          // [BC][KAUG]    hy | x_t per local batch
    float* partial = a_s + BC * KAUG;            // [KSLICES][BC][CC]
    float* bias_s  = partial + KSLICES * BC * CC;
    float* gamma_s = bias_s + CC;
    float* eps_s   = gamma_s + CC;

    const int tid = threadIdx.x;
    const int g   = blockIdx.x >> 3;     // batch group 0..15
    const int j   = blockIdx.x & 7;      // column slice 0..7
    const int b0  = g * BC;              // global batch base
    const int cg0 = j * CC;              // global column base

    const int ks = tid >> 6;             // k-slice 0..7 (main loop role)
    const int c  = tid & 63;             // local column 0..63
    const int eb = tid >> 6;             // local batch 0..7 (elementwise role)

    // ---- Prologue: load augmented weights (h2h rows 0..511, x2h rows 512..575) ----
    for (int idx = tid; idx < KAUG * CC; idx += NTHREADS) {
        int k  = idx >> 6;
        int cc = idx & 63;
        float w = (k < H_) ? h2h[(size_t)k * H_ + cg0 + cc]
                           : x2h[(size_t)(k - H_) * H_ + cg0 + cc];
        W_s[cc * WPITCH + k] = w;
    }
    if (tid < CC) {
        bias_s[tid]  = bias [cg0 + tid];
        gamma_s[tid] = gamma_[cg0 + tid];
        eps_s[tid]   = eps_ [cg0 + tid];
    }
    // a_s init: hy = 0, x part = x[:, 0, :]
    for (int idx = tid; idx < BC * H_; idx += NTHREADS) {
        int b = idx >> 9, k = idx & 511;
        a_s[b * KAUG + k] = 0.0f;
    }
    {
        int b = tid >> 6, k2 = tid & 63;
        a_s[b * KAUG + H_ + k2] = x[((size_t)(b0 + b) * T_ + 0) * I_ + k2];
    }
    __syncthreads();

    float hz = 0.0f;   // per (eb, c) pair, persistent across steps

    const float4* Ws4 = reinterpret_cast<const float4*>(W_s) + ((size_t)c * (WPITCH / 4) + ks * KCHUNK4);
    const float4* As4 = reinterpret_cast<const float4*>(a_s);

    for (int t = 0; t < T_; t++) {
        // ---- Matvec: acc[b] = sum over this thread's k-chunk of a[b][k] * W[k][c] ----
        float acc[BC];
        #pragma unroll
        for (int b = 0; b < BC; b++) acc[b] = 0.0f;

        #pragma unroll
        for (int kb = 0; kb < KCHUNK4; kb++) {
            float4 wv = Ws4[kb];
            #pragma unroll
            for (int b = 0; b < BC; b++) {
                float4 av = As4[b * AROW4 + ks * KCHUNK4 + kb];
                acc[b] = fmaf(av.x, wv.x, acc[b]);
                acc[b] = fmaf(av.y, wv.y, acc[b]);
                acc[b] = fmaf(av.z, wv.z, acc[b]);
                acc[b] = fmaf(av.w, wv.w, acc[b]);
            }
        }

        // ---- k-split reduction through SMEM ----
        #pragma unroll
        for (int b = 0; b < BC; b++)
            partial[ks * (BC * CC) + b * CC + c] = acc[b];
        __syncthreads();

        float v = 0.0f;
        #pragma unroll
        for (int s2 = 0; s2 < KSLICES; s2++)
            v += partial[s2 * (BC * CC) + eb * CC + c];

        // ---- Elementwise oscillator update for pair (eb, c) ----
        float pre  = v + bias_s[c];                 // u + hy @ h2h
        float act  = tanhf(pre);
        float hyo  = a_s[eb * KAUG + cg0 + c];      // old hy
        hz         = hz + DT_F * (act - gamma_s[c] * hyo - eps_s[c] * hz);
        float hyn  = hyo + DT_F * hz;

        out[((size_t)(b0 + eb) * T_ + t) * H_ + cg0 + c] = hyn;
        if (write_tail && t == T_ - 1)
            out[(size_t)B_ * T_ * H_ + (size_t)(b0 + eb) * H_ + cg0 + c] = hyn;

        if (t + 1 == T_) break;   // uniform across all CTAs — no final exchange needed

        // ---- Exchange: publish hy slice, barrier, refill a_s ----
        const int p = t & 1;
        __stcg(&g_hy_ex[p][g][eb][cg0 + c], hyn);

        __threadfence();
        __syncthreads();
        if (tid == 0) {
            red_release_add(&g_bar[g], 1u);
            const unsigned target = (unsigned)(NCOL * (t + 1));
            while (ld_acquire_u32(&g_bar[g]) < target) { }
        }
        __syncthreads();

        #pragma unroll
        for (int i = 0; i < 8; i++) {
            int idx = tid + i * NTHREADS;      // 0..4095
            int b = idx >> 9, k = idx & 511;
            a_s[b * KAUG + k] = __ldcg(&g_hy_ex[p][g][b][k]);
        }
        {
            int b = tid >> 6, k2 = tid & 63;
            a_s[b * KAUG + H_ + k2] = x[((size_t)(b0 + b) * T_ + (t + 1)) * I_ + k2];
        }
        __syncthreads();
    }
}

extern "C" void kernel_launch(void* const* d_in, const int* in_sizes, int n_in,
                              void* d_out, int out_size)
{
    const float* x     = (const float*)d_in[0];  // [128,1024,64]
    const float* x2h   = (const float*)d_in[1];  // [64,512]
    const float* h2h   = (const float*)d_in[2];  // [512,512]
    const float* bias  = (const float*)d_in[3];  // [512]
    const float* gamma_ = (const float*)d_in[4]; // [512]
    const float* eps_  = (const float*)d_in[5];  // [512]
    float* out = (float*)d_out;

    const int smem_bytes = (CC * WPITCH + BC * KAUG + KSLICES * BC * CC + 3 * CC) * 4; // 184064
    cudaFuncSetAttribute(ron_scan_kernel,
                         cudaFuncAttributeMaxDynamicSharedMemorySize, smem_bytes);

    const int write_tail = (out_size > B_ * T_ * H_) ? 1 : 0;

    ron_init_kernel<<<1, 32>>>();
    ron_scan_kernel<<<NGRP * NCOL, NTHREADS, smem_bytes>>>(
        x, x2h, h2h, bias, gamma_, eps_, out, write_tail);
}

// round 2
// speedup vs baseline: 1.4304x; 1.4304x over previous
#include <cuda_runtime.h>
#include <cstdint>

// RandomizedOscillatorsNetwork: B=128, T=1024, I=64, H=512, dt=0.042
// Persistent kernel: 128 CTAs = 16 batch-groups x 8 column-slices.
// R1 changes: Tc=2 register tiling (KSLICES=16), no all-thread threadfence,
// hy in registers, own-slice STS, x[t+1] prefetch.

#define DT_F      0.042f
#define B_        128
#define T_        1024
#define I_        64
#define H_        512
#define KAUG      576           // H_ + I_
#define NCOL      8
#define NGRP      16
#define BC        8             // batches per CTA
#define CC        64            // columns per CTA
#define WPITCH    580           // 4*odd -> conflict-free float4 LDS
#define NTHREADS  512
#define KSLICES   16
#define KCHUNK4   9             // float4 per k-slice (36 floats)
#define AROW4     (KAUG / 4)    // 144
#define WROW4     (WPITCH / 4)  // 145

__device__ unsigned g_bar[NGRP];
__device__ float    g_hy_ex[2][NGRP][BC][H_];

__device__ __forceinline__ unsigned ld_acquire_u32(const unsigned* p) {
    unsigned v;
    asm volatile("ld.acquire.gpu.u32 %0, [%1];" : "=r"(v) : "l"(p) : "memory");
    return v;
}
__device__ __forceinline__ void red_release_add(unsigned* p, unsigned v) {
    asm volatile("red.release.gpu.global.add.u32 [%0], %1;" :: "l"(p), "r"(v) : "memory");
}

__global__ void ron_init_kernel() {
    if (threadIdx.x < NGRP) g_bar[threadIdx.x] = 0u;
}

__global__ void __launch_bounds__(NTHREADS, 1)
ron_scan_kernel(const float* __restrict__ x,      // [B, T, I]
                const float* __restrict__ x2h,    // [I, H]
                const float* __restrict__ h2h,    // [H, H]
                const float* __restrict__ bias,   // [H]
                const float* __restrict__ gamma_, // [H]
                const float* __restrict__ eps_,   // [H]
                float* __restrict__ out,          // [B*T*H] (+ optional [B*H] tail)
                int write_tail)
{
    extern __shared__ float smem[];
    float* W_s     = smem;                        // [CC][WPITCH]  augmented weights, c-major
    float* a_s     = W_s + CC * WPITCH;           // [BC][KAUG]    hy | x_t
    float* partial = a_s + BC * KAUG;             // [KSLICES][BC][CC]

    const int tid = threadIdx.x;
    const int g   = blockIdx.x >> 3;
    const int j   = blockIdx.x & 7;
    const int b0  = g * BC;
    const int cg0 = j * CC;

    // matvec role
    const int ks  = tid >> 5;            // 0..15 k-slice
    const int c0  = tid & 31;            // local column (pair: c0, c0+32)
    // elementwise role
    const int eb  = tid >> 6;            // 0..7 local batch
    const int ec  = tid & 63;            // 0..63 local column

    // ---- Prologue ----
    for (int idx = tid; idx < KAUG * CC; idx += NTHREADS) {
        int k  = idx >> 6;
        int cc = idx & 63;
        float w = (k < H_) ? h2h[(size_t)k * H_ + cg0 + cc]
                           : x2h[(size_t)(k - H_) * H_ + cg0 + cc];
        W_s[cc * WPITCH + k] = w;
    }
    for (int idx = tid; idx < BC * H_; idx += NTHREADS) {
        int b = idx >> 9, k = idx & 511;
        a_s[b * KAUG + k] = 0.0f;
    }
    a_s[eb * KAUG + H_ + ec] = x[((size_t)(b0 + eb) * T_ + 0) * I_ + ec];

    const float bia = bias  [cg0 + ec];
    const float gam = gamma_[cg0 + ec];
    const float ep  = eps_  [cg0 + ec];

    __syncthreads();

    float hy_reg = 0.0f, hz = 0.0f;

    const float4* p0 = reinterpret_cast<const float4*>(W_s) + (size_t)c0 * WROW4 + ks * KCHUNK4;
    const float4* p1 = p0 + 32 * WROW4;
    const float4* A4 = reinterpret_cast<const float4*>(a_s) + ks * KCHUNK4;

    for (int t = 0; t < T_; t++) {
        // prefetch next-step input (latency hidden under matvec)
        float xnext = 0.0f;
        if (t + 1 < T_)
            xnext = x[((size_t)(b0 + eb) * T_ + (t + 1)) * I_ + ec];

        // ---- Matvec: Tc=2 columns x Tb=8 batches per thread over its k-chunk ----
        float acc0[BC], acc1[BC];
        #pragma unroll
        for (int b = 0; b < BC; b++) { acc0[b] = 0.0f; acc1[b] = 0.0f; }

        #pragma unroll
        for (int kb = 0; kb < KCHUNK4; kb++) {
            float4 w0 = p0[kb];
            float4 w1 = p1[kb];
            #pragma unroll
            for (int b = 0; b < BC; b++) {
                float4 av = A4[b * AROW4 + kb];
                acc0[b] = fmaf(av.x, w0.x, acc0[b]);
                acc0[b] = fmaf(av.y, w0.y, acc0[b]);
                acc0[b] = fmaf(av.z, w0.z, acc0[b]);
                acc0[b] = fmaf(av.w, w0.w, acc0[b]);
                acc1[b] = fmaf(av.x, w1.x, acc1[b]);
                acc1[b] = fmaf(av.y, w1.y, acc1[b]);
                acc1[b] = fmaf(av.z, w1.z, acc1[b]);
                acc1[b] = fmaf(av.w, w1.w, acc1[b]);
            }
        }

        // ---- k-split partial stores ----
        #pragma unroll
        for (int b = 0; b < BC; b++) {
            partial[ks * (BC * CC) + b * CC + c0]      = acc0[b];
            partial[ks * (BC * CC) + b * CC + c0 + 32] = acc1[b];
        }
        __syncthreads();

        // ---- reduce + oscillator update (per (eb, ec)) ----
        float v = 0.0f;
        #pragma unroll
        for (int s = 0; s < KSLICES; s++)
            v += partial[s * (BC * CC) + eb * CC + ec];

        float act = tanhf(v + bia);
        hz     = hz + DT_F * (act - gam * hy_reg - ep * hz);
        hy_reg = hy_reg + DT_F * hz;

        out[((size_t)(b0 + eb) * T_ + t) * H_ + cg0 + ec] = hy_reg;
        if (write_tail && t == T_ - 1)
            out[(size_t)B_ * T_ * H_ + (size_t)(b0 + eb) * H_ + cg0 + ec] = hy_reg;

        if (t + 1 == T_) break;

        // own hy slice straight into a_s (no global round-trip for it)
        a_s[eb * KAUG + cg0 + ec] = hy_reg;

        // publish for peer CTAs (L2-resident, double-buffered)
        const int p = t & 1;
        __stcg(&g_hy_ex[p][g][eb][cg0 + ec], hy_reg);

        __syncthreads();
        if (tid == 0) {
            red_release_add(&g_bar[g], 1u);
            const unsigned target = (unsigned)(NCOL * (t + 1));
            while (ld_acquire_u32(&g_bar[g]) < target) { }
        }
        __syncthreads();

        // refill foreign hy slices
        #pragma unroll
        for (int i = 0; i < 8; i++) {
            int idx = tid + i * NTHREADS;
            int b = idx >> 9, k = idx & 511;
            if ((k >> 6) != j)
                a_s[b * KAUG + k] = __ldcg(&g_hy_ex[p][g][b][k]);
        }
        a_s[eb * KAUG + H_ + ec] = xnext;
        __syncthreads();
    }
}

extern "C" void kernel_launch(void* const* d_in, const int* in_sizes, int n_in,
                              void* d_out, int out_size)
{
    const float* x      = (const float*)d_in[0];
    const float* x2h    = (const float*)d_in[1];
    const float* h2h    = (const float*)d_in[2];
    const float* bias   = (const float*)d_in[3];
    const float* gamma_ = (const float*)d_in[4];
    const float* eps_   = (const float*)d_in[5];
    float* out = (float*)d_out;

    const int smem_bytes = (CC * WPITCH + BC * KAUG + KSLICES * BC * CC) * 4; // 199,680 B
    cudaFuncSetAttribute(ron_scan_kernel,
                         cudaFuncAttributeMaxDynamicSharedMemorySize, smem_bytes);

    const int write_tail = (out_size > B_ * T_ * H_) ? 1 : 0;

    ron_init_kernel<<<1, 32>>>();
    ron_scan_kernel<<<NGRP * NCOL, NTHREADS, smem_bytes>>>(
        x, x2h, h2h, bias, gamma_, eps_, out, write_tail);
}